// round 17
// baseline (speedup 1.0000x reference)
#include <cuda_runtime.h>
#include <cstdint>

#define TT   512
#define BB   1024
#define H1   64
#define H2   32
#define G2   128     // 4*H2

// h1 scratch, PACKED f16x2: g_h1p[(t*BB+b)*64 + dir*32 + cellpair]
__device__ uint32_t g_h1p[(size_t)TT * BB * 64];

// ---- fp32 fast activations --------------------------------------------------
__device__ __forceinline__ float tanh_(float x) {
    float y;
    asm("tanh.approx.f32 %0, %1;" : "=f"(y) : "f"(x));
    return y;
}
__device__ __forceinline__ float sigm(float x) {
    return fmaf(tanh_(x * 0.5f), 0.5f, 0.5f);
}

// ---- f16x2 helpers ------------------------------------------------------------
#define H05 0x38003800u   // half2(0.5, 0.5)

__device__ __forceinline__ uint32_t pack_f16(float lo, float hi) {
    uint32_t r;
    asm("cvt.rn.f16x2.f32 %0, %1, %2;" : "=r"(r) : "f"(hi), "f"(lo));
    return r;
}
__device__ __forceinline__ float f16_lo(uint32_t u) {
    float f;
    asm("{.reg .b16 l, h; mov.b32 {l, h}, %1; cvt.f32.f16 %0, l;}" : "=f"(f) : "r"(u));
    return f;
}
__device__ __forceinline__ float f16_hi(uint32_t u) {
    float f;
    asm("{.reg .b16 l, h; mov.b32 {l, h}, %1; cvt.f32.f16 %0, h;}" : "=f"(f) : "r"(u));
    return f;
}
__device__ __forceinline__ uint32_t h2mul(uint32_t a, uint32_t b) {
    uint32_t d;
    asm("mul.rn.f16x2 %0, %1, %2;" : "=r"(d) : "r"(a), "r"(b));
    return d;
}
__device__ __forceinline__ uint32_t h2fma(uint32_t a, uint32_t b, uint32_t c) {
    uint32_t d;
    asm("fma.rn.f16x2 %0, %1, %2, %3;" : "=r"(d) : "r"(a), "r"(b), "r"(c));
    return d;
}
__device__ __forceinline__ uint32_t h2add(uint32_t a, uint32_t b) {
    uint32_t d;
    asm("add.rn.f16x2 %0, %1, %2;" : "=r"(d) : "r"(a), "r"(b));
    return d;
}
__device__ __forceinline__ uint32_t tanh2(uint32_t x) {
    uint32_t d;
    asm("tanh.approx.f16x2 %0, %1;" : "=r"(d) : "r"(x));
    return d;
}
__device__ __forceinline__ uint32_t sigm2(uint32_t x) {
    return h2fma(tanh2(h2mul(x, H05)), H05, H05);
}

__device__ __forceinline__ void mma_f16(float& c0, float& c1, float& c2, float& c3,
                                        uint32_t a0, uint32_t a1, uint32_t a2, uint32_t a3,
                                        uint32_t b0, uint32_t b1) {
    asm("mma.sync.aligned.m16n8k16.row.col.f32.f16.f16.f32 "
        "{%0,%1,%2,%3}, {%4,%5,%6,%7}, {%8,%9}, {%0,%1,%2,%3};"
        : "+f"(c0), "+f"(c1), "+f"(c2), "+f"(c3)
        : "r"(a0), "r"(a1), "r"(a2), "r"(a3), "r"(b0), "r"(b1));
}

// ---- cp.async helpers -------------------------------------------------------
__device__ __forceinline__ uint32_t smem_u32(const void* p) {
    return (uint32_t)__cvta_generic_to_shared(p);
}
#define CP_ASYNC16(dst, src) \
    asm volatile("cp.async.ca.shared.global [%0], [%1], 16;" :: "r"(dst), "l"(src))
#define CP_COMMIT() asm volatile("cp.async.commit_group;")
#define CP_WAIT(n)  asm volatile("cp.async.wait_group %0;" :: "n"(n))

// ---------------------------------------------------------------------------
// Kernel 1: bidirectional layer-1 LSTM via fp16 m16n8k16 tensor cores with
// f16x2 SIMD cell math (10 MUFU/thread/step).  grid = (64, 2), block = 256,
// 16 batches/block, 1 barrier/step, h packed f16x2 in smem and g_h1p.
// ---------------------------------------------------------------------------
__global__ __launch_bounds__(256, 1)
void lstm1_tc(const float* __restrict__ x,
              const float* __restrict__ wih_f, const float* __restrict__ whh_f,
              const float* __restrict__ b_f,
              const float* __restrict__ wih_r, const float* __restrict__ whh_r,
              const float* __restrict__ b_r)
{
    const int dir  = blockIdx.y;
    const int b0   = blockIdx.x * 16;
    const int tid  = threadIdx.x;
    const int w    = tid >> 5;
    const int lane = tid & 31;
    const int gid  = lane >> 2;          // 0..7
    const int tig  = lane & 3;

    const float* wih = dir ? wih_r : wih_f;
    const float* whh = dir ? whh_r : whh_f;
    const float* bb  = dir ? b_r  : b_f;

    __shared__ float    sxc[16][64];     // 4 KB x chunk
    __shared__ uint32_t hs[2][16][36];   // packed f16x2 h (32 pairs + pad)

    // Whh B-fragments (f16x2) in registers: [gate q][k16-chunk][2]
    uint32_t bf[4][4][2];
#pragma unroll
    for (int q = 0; q < 4; q++) {
        const int n = 64 * q + 8 * w + gid;
#pragma unroll
        for (int kc = 0; kc < 4; kc++) {
            const int k0 = 16 * kc + 2 * tig;
            bf[q][kc][0] = pack_f16(whh[n * 64 + k0],     whh[n * 64 + k0 + 1]);
            bf[q][kc][1] = pack_f16(whh[n * 64 + k0 + 8], whh[n * 64 + k0 + 9]);
        }
    }
    const int cell0 = 8 * w + 2 * tig;
    float wi[4][2], bs4[4][2];
#pragma unroll
    for (int q = 0; q < 4; q++) {
        wi[q][0]  = wih[64 * q + cell0];
        wi[q][1]  = wih[64 * q + cell0 + 1];
        bs4[q][0] = bb[64 * q + cell0];
        bs4[q][1] = bb[64 * q + cell0 + 1];
    }

    for (int i = tid; i < 16 * 36; i += 256) ((uint32_t*)hs[0])[i] = 0u;

    // packed cell states: cc2[0] = (gid, cell0/cell0+1), cc2[1] = (gid+8, ...)
    uint32_t cc2[2] = {0u, 0u};
    const int pidx = 4 * w + tig;        // pair index of (cell0, cell0+1)

    __syncthreads();

    for (int tt = 0; tt < TT; ++tt) {
        const int t   = tt ^ (dir ? (TT - 1) : 0);   // dir ? TT-1-tt : tt
        const int cur = tt & 1;
        const int nxt = cur ^ 1;

        if ((tt & 63) == 0) {
            const int tbase = dir ? (448 - tt) : tt;
            for (int i = tid; i < 16 * 64; i += 256) {
                int b = i >> 6, to = i & 63;
                sxc[b][to] = x[(size_t)(b0 + b) * TT + tbase + to];
            }
            __syncthreads();
        }
        const int ts = t & 63;

        const float xv0 = sxc[gid][ts];
        const float xv1 = sxc[gid + 8][ts];
        float c[4][4];
#pragma unroll
        for (int q = 0; q < 4; q++) {
            c[q][0] = fmaf(xv0, wi[q][0], bs4[q][0]);
            c[q][1] = fmaf(xv0, wi[q][1], bs4[q][1]);
            c[q][2] = fmaf(xv1, wi[q][0], bs4[q][0]);
            c[q][3] = fmaf(xv1, wi[q][1], bs4[q][1]);
        }

#pragma unroll
        for (int kc = 0; kc < 4; kc++) {
            uint32_t a0 = hs[cur][gid][8 * kc + tig];
            uint32_t a1 = hs[cur][gid + 8][8 * kc + tig];
            uint32_t a2 = hs[cur][gid][8 * kc + tig + 4];
            uint32_t a3 = hs[cur][gid + 8][8 * kc + tig + 4];
#pragma unroll
            for (int q = 0; q < 4; q++)
                mma_f16(c[q][0], c[q][1], c[q][2], c[q][3],
                        a0, a1, a2, a3, bf[q][kc][0], bf[q][kc][1]);
        }

        // f16x2 SIMD cell update: 2 pairs (batch gid, gid+8)
        uint32_t hp[2];
#pragma unroll
        for (int p = 0; p < 2; p++) {
            uint32_t zi = pack_f16(c[0][2 * p], c[0][2 * p + 1]);
            uint32_t zf = pack_f16(c[1][2 * p], c[1][2 * p + 1]);
            uint32_t zg = pack_f16(c[2][2 * p], c[2][2 * p + 1]);
            uint32_t zo = pack_f16(c[3][2 * p], c[3][2 * p + 1]);
            uint32_t si = sigm2(zi), sf = sigm2(zf), so = sigm2(zo);
            uint32_t tg = tanh2(zg);
            cc2[p] = h2fma(sf, cc2[p], h2mul(si, tg));
            hp[p]  = h2mul(so, tanh2(cc2[p]));
        }

        hs[nxt][gid][pidx]     = hp[0];
        hs[nxt][gid + 8][pidx] = hp[1];

        g_h1p[((size_t)t * BB + b0 + gid) * 64 + dir * 32 + pidx]     = hp[0];
        g_h1p[((size_t)t * BB + b0 + gid + 8) * 64 + dir * 32 + pidx] = hp[1];

        __syncthreads();   // single barrier per step
    }
}

// ---------------------------------------------------------------------------
// Kernel 2 (FUSED): layer-2 forward scan with in-kernel input projection,
// fp16 m16n8k16, f16x2 cell math; + single reverse step + MLP head.
// grid = 128, block = 256 (8 warps), 8 batches/block.
// ---------------------------------------------------------------------------
__global__ __launch_bounds__(256, 1)
void lstm2_fused(const float* __restrict__ wih2f, const float* __restrict__ whh2f,
                 const float* __restrict__ b2f,
                 const float* __restrict__ wih2r, const float* __restrict__ b2r,
                 const float* __restrict__ w_fc1, const float* __restrict__ b_fc1,
                 const float* __restrict__ w_out, const float* __restrict__ b_out,
                 float* __restrict__ out)
{
    const int b0   = blockIdx.x * 8;
    const int tid  = threadIdx.x;
    const int w    = tid >> 5;
    const int lane = tid & 31;
    const int gid  = lane >> 2;          // 0..7 (batch row)
    const int tig  = lane & 3;

    __shared__ uint32_t hst[4][8][68];   // h1 tile ring, packed f16x2
    __shared__ uint32_t hh2[2][8][20];   // h2 packed f16x2, double-buffered
    __shared__ float    zbuf[8][132];    // gate pre-activations (no bias)
    __shared__ float    slast[8][64];
    __shared__ float    sfc[8][64];

    // Wcat B-fragments (f16x2): warp owns gates [16w,16w+16) = 2 n-tiles; k=160
    uint32_t wb[2][10][2];
#pragma unroll
    for (int nt = 0; nt < 2; nt++) {
        const int n = 16 * w + 8 * nt + gid;
#pragma unroll
        for (int kc = 0; kc < 10; kc++) {
            const int k0 = 16 * kc + 2 * tig;
            float f0 = (k0 < 128)     ? wih2f[n * 128 + k0]     : whh2f[n * 32 + k0 - 128];
            float f1 = (k0 + 1 < 128) ? wih2f[n * 128 + k0 + 1] : whh2f[n * 32 + k0 - 127];
            float f2 = (k0 + 8 < 128) ? wih2f[n * 128 + k0 + 8] : whh2f[n * 32 + k0 - 120];
            float f3 = (k0 + 9 < 128) ? wih2f[n * 128 + k0 + 9] : whh2f[n * 32 + k0 - 119];
            wb[nt][kc][0] = pack_f16(f0, f1);
            wb[nt][kc][1] = pack_f16(f2, f3);
        }
    }

    // cell phase: 128 threads, thread -> (batch pb, cell pair pj)
    const int pb  = tid >> 4;            // 0..7 (tid<128)
    const int pj  = tid & 15;            // pair index 0..15
    const int pj2 = pj * 2;
    uint32_t bi2 = 0u, bf2 = 0u, bg2 = 0u, bo2 = 0u;
    if (tid < 128) {
        bi2 = pack_f16(b2f[pj2],      b2f[pj2 + 1]);
        bf2 = pack_f16(b2f[32 + pj2], b2f[33 + pj2]);
        bg2 = pack_f16(b2f[64 + pj2], b2f[65 + pj2]);
        bo2 = pack_f16(b2f[96 + pj2], b2f[97 + pj2]);
    }
    uint32_t cst2 = 0u;
    uint32_t hlp  = 0u;                  // final forward h2 pair (f16x2)

    for (int i = tid; i < 2 * 8 * 20; i += 256) ((uint32_t*)hh2)[i] = 0u;

    // staging role (tid<128): batch sb, 4 uint32 at sk
    const int sb = tid >> 4;
    const int sk = (tid & 15) * 4;

    // prologue: issue tiles t=0..2
#pragma unroll
    for (int p = 0; p < 3; p++) {
        if (tid < 128)
            CP_ASYNC16(smem_u32(&hst[p][sb][sk]),
                       g_h1p + ((size_t)p * BB + b0 + sb) * 64 + sk);
        CP_COMMIT();
    }

    for (int t = 0; t < TT; ++t) {
        const int cur = t & 3;
        const int hb  = t & 1;

        CP_WAIT(2);          // tile t complete
        __syncthreads();     // + hh2/zbuf handoff from previous step

        if (t + 3 < TT && tid < 128) {
            CP_ASYNC16(smem_u32(&hst[(t + 3) & 3][sb][sk]),
                       g_h1p + ((size_t)(t + 3) * BB + b0 + sb) * 64 + sk);
        }
        CP_COMMIT();

        // z = [h1 | h2] @ Wcat^T  (m rows 8-15 zero via a1=a3=0)
        float c[2][4] = {{0.f, 0.f, 0.f, 0.f}, {0.f, 0.f, 0.f, 0.f}};
#pragma unroll
        for (int kc = 0; kc < 8; kc++) {
            uint32_t a0 = hst[cur][gid][8 * kc + tig];
            uint32_t a2 = hst[cur][gid][8 * kc + tig + 4];
            mma_f16(c[0][0], c[0][1], c[0][2], c[0][3],
                    a0, 0u, a2, 0u, wb[0][kc][0], wb[0][kc][1]);
            mma_f16(c[1][0], c[1][1], c[1][2], c[1][3],
                    a0, 0u, a2, 0u, wb[1][kc][0], wb[1][kc][1]);
        }
#pragma unroll
        for (int kc = 8; kc < 10; kc++) {
            uint32_t a0 = hh2[hb][gid][8 * (kc - 8) + tig];
            uint32_t a2 = hh2[hb][gid][8 * (kc - 8) + tig + 4];
            mma_f16(c[0][0], c[0][1], c[0][2], c[0][3],
                    a0, 0u, a2, 0u, wb[0][kc][0], wb[0][kc][1]);
            mma_f16(c[1][0], c[1][1], c[1][2], c[1][3],
                    a0, 0u, a2, 0u, wb[1][kc][0], wb[1][kc][1]);
        }

        *(float2*)&zbuf[gid][16 * w + 2 * tig]     = make_float2(c[0][0], c[0][1]);
        *(float2*)&zbuf[gid][16 * w + 8 + 2 * tig] = make_float2(c[1][0], c[1][1]);
        __syncthreads();

        // f16x2 SIMD cell update: one pair per thread (tid<128)
        if (tid < 128) {
            uint32_t zi = h2add(pack_f16(zbuf[pb][pj2],      zbuf[pb][pj2 + 1]),  bi2);
            uint32_t zf = h2add(pack_f16(zbuf[pb][32 + pj2], zbuf[pb][33 + pj2]), bf2);
            uint32_t zg = h2add(pack_f16(zbuf[pb][64 + pj2], zbuf[pb][65 + pj2]), bg2);
            uint32_t zo = h2add(pack_f16(zbuf[pb][96 + pj2], zbuf[pb][97 + pj2]), bo2);
            uint32_t si = sigm2(zi), sf = sigm2(zf), so = sigm2(zo);
            uint32_t tg = tanh2(zg);
            cst2 = h2fma(sf, cst2, h2mul(si, tg));
            hlp  = h2mul(so, tanh2(cst2));
            hh2[hb ^ 1][pb][pj] = hlp;
        }
        // next iteration's top barrier orders hh2/zbuf handoff
    }

    __syncthreads();
    // hst[3] = h1[T-1] tile (issued at t=508, untouched since).

    // layer-2 reverse: single step at t = T-1 from h=c=0 (fp32 math)
    {
        const int g2 = tid & 127;
        const int hf = tid >> 7;
        const float brv = b2r[g2];
        float a[4] = {brv, brv, brv, brv};
        const float* wr = wih2r + g2 * G2;
        for (int p = 0; p < 64; p++) {
            float w0 = __ldg(wr + 2 * p);
            float w1 = __ldg(wr + 2 * p + 1);
#pragma unroll
            for (int b = 0; b < 4; b++) {
                uint32_t u = hst[3][hf * 4 + b][p];
                a[b] = fmaf(f16_lo(u), w0, a[b]);
                a[b] = fmaf(f16_hi(u), w1, a[b]);
            }
        }
#pragma unroll
        for (int b = 0; b < 4; b++) zbuf[hf * 4 + b][g2] = a[b];
    }
    __syncthreads();
    if (tid < 128) {
        // reverse cells pj2, pj2+1 for batch pb  (c_prev = 0)
        float zi0 = zbuf[pb][pj2],      zi1 = zbuf[pb][pj2 + 1];
        float zg0 = zbuf[pb][64 + pj2], zg1 = zbuf[pb][65 + pj2];
        float zo0 = zbuf[pb][96 + pj2], zo1 = zbuf[pb][97 + pj2];
        float cr0 = sigm(zi0) * tanh_(zg0);
        float cr1 = sigm(zi1) * tanh_(zg1);
        slast[pb][pj2]          = f16_lo(hlp);
        slast[pb][pj2 + 1]      = f16_hi(hlp);
        slast[pb][32 + pj2]     = sigm(zo0) * tanh_(cr0);
        slast[pb][32 + pj2 + 1] = sigm(zo1) * tanh_(cr1);
    }
    __syncthreads();

    // fc1 (64x64) + relu: 512 items, 2 per thread
#pragma unroll
    for (int rep = 0; rep < 2; rep++) {
        int item = tid + rep * 256;
        int b = item >> 6, o = item & 63;
        float a = b_fc1[o];
        const float* wf = w_fc1 + o * 64;
        for (int k = 0; k < 64; k++) a = fmaf(slast[b][k], __ldg(wf + k), a);
        sfc[b][o] = fmaxf(a, 0.f);
    }
    __syncthreads();

    if (tid < 8) {
        float a = b_out[0];
        for (int k = 0; k < 64; k++) a = fmaf(sfc[tid][k], __ldg(w_out + k), a);
        out[b0 + tid] = sigm(a);
    }
}

// ---------------------------------------------------------------------------
extern "C" void kernel_launch(void* const* d_in, const int* in_sizes, int n_in,
                              void* d_out, int out_size)
{
    (void)in_sizes; (void)n_in; (void)out_size;
    const float* x     = (const float*)d_in[0];
    const float* wih1f = (const float*)d_in[1];
    const float* whh1f = (const float*)d_in[2];
    const float* b1f   = (const float*)d_in[3];
    const float* wih1r = (const float*)d_in[4];
    const float* whh1r = (const float*)d_in[5];
    const float* b1r   = (const float*)d_in[6];
    const float* wih2f = (const float*)d_in[7];
    const float* whh2f = (const float*)d_in[8];
    const float* b2f   = (const float*)d_in[9];
    const float* wih2r = (const float*)d_in[10];
    const float* b2r   = (const float*)d_in[12];
    const float* w_fc1 = (const float*)d_in[13];
    const float* b_fc1 = (const float*)d_in[14];
    const float* w_out = (const float*)d_in[15];
    const float* b_out = (const float*)d_in[16];
    float* out = (float*)d_out;

    lstm1_tc<<<dim3(BB / 16, 2), 256>>>(x, wih1f, whh1f, b1f, wih1r, whh1r, b1r);
    lstm2_fused<<<BB / 8, 256>>>(wih2f, whh2f, b2f, wih2r, b2r,
                                 w_fc1, b_fc1, w_out, b_out, out);
}